// round 15
// baseline (speedup 1.0000x reference)
#include <cuda_runtime.h>
#include <cstdint>

// ---------------- problem constants ----------------
#define NCC   29
#define NIMG  3
#define NHID  16
#define NOUT  10
#define B_    16
#define HW_   64
#define PIX   4096           // 64*64
#define INVEC 88             // 3*29+1
#define NT    256

typedef unsigned long long u64;

// ---------------- packed f32x2 helpers (bit-exact vs scalar FP32) ----------
__device__ __forceinline__ u64 bcast2(float a) {
    u64 r; asm("mov.b64 %0, {%1, %1};" : "=l"(r) : "f"(a)); return r;
}
__device__ __forceinline__ void unpack2(u64 v, float& a, float& b) {
    asm("mov.b64 {%0, %1}, %2;" : "=f"(a), "=f"(b) : "l"(v));
}
__device__ __forceinline__ u64 ffma2(u64 a, u64 b, u64 c) {
    u64 d; asm("fma.rn.f32x2 %0, %1, %2, %3;" : "=l"(d) : "l"(a), "l"(b), "l"(c));
    return d;
}

// ---------------- cp.async helpers ----------------
__device__ __forceinline__ void cpa16(uint32_t dst, const void* src) {
    asm volatile("cp.async.ca.shared.global [%0], [%1], 16;" :: "r"(dst), "l"(src));
}
#define CP_COMMIT() asm volatile("cp.async.commit_group;" ::: "memory")
#define CP_WAIT0()  asm volatile("cp.async.wait_group 0;" ::: "memory")

// ---------------- persistent device buffers (no allocation allowed) ----------
__device__ float g_bufA[B_ * NCC * PIX];
__device__ float g_bufB[B_ * NCC * PIX];
__device__ float g_w1t[96 * 256];    // [k(pad 96)][o=256]
__device__ float g_w2t[256 * 128];   // [k=256][o=128]
__device__ float g_w3t[128 * 32];    // [k=128][o(pad 32)]

// ---------------- JAX threefry2x32 (bit exact) ----------------
__device__ __forceinline__ void tf2x32(unsigned k0, unsigned k1,
                                       unsigned x0, unsigned x1,
                                       unsigned& o0, unsigned& o1) {
    unsigned ks2 = k0 ^ k1 ^ 0x1BD11BDAu;
    x0 += k0; x1 += k1;
#define TFR(r) { x0 += x1; x1 = (x1 << (r)) | (x1 >> (32 - (r))); x1 ^= x0; }
    TFR(13) TFR(15) TFR(26) TFR(6)
    x0 += k1;  x1 += ks2 + 1u;
    TFR(17) TFR(29) TFR(16) TFR(24)
    x0 += ks2; x1 += k0 + 2u;
    TFR(13) TFR(15) TFR(26) TFR(6)
    x0 += k0;  x1 += k1 + 3u;
    TFR(17) TFR(29) TFR(16) TFR(24)
    x0 += k1;  x1 += ks2 + 4u;
    TFR(13) TFR(15) TFR(26) TFR(6)
    x0 += ks2; x1 += k0 + 5u;
#undef TFR
    o0 = x0; o1 = x1;
}

// XLA ErfInv32 (Giles polynomials) — matches jax.random.normal
__device__ __forceinline__ float erfinv_xla(float x) {
    float w = -log1pf(-x * x);
    float p;
    if (w < 5.0f) {
        w -= 2.5f;
        p = 2.81022636e-08f;
        p = fmaf(p, w, 3.43273939e-07f);
        p = fmaf(p, w, -3.5233877e-06f);
        p = fmaf(p, w, -4.39150654e-06f);
        p = fmaf(p, w, 0.00021858087f);
        p = fmaf(p, w, -0.00125372503f);
        p = fmaf(p, w, -0.00417768164f);
        p = fmaf(p, w, 0.246640727f);
        p = fmaf(p, w, 1.50140941f);
    } else {
        w = sqrtf(w) - 3.0f;
        p = -0.000200214257f;
        p = fmaf(p, w, 0.000100950558f);
        p = fmaf(p, w, 0.00134934322f);
        p = fmaf(p, w, -0.00367342844f);
        p = fmaf(p, w, 0.00573950773f);
        p = fmaf(p, w, -0.0076224613f);
        p = fmaf(p, w, 0.00943887047f);
        p = fmaf(p, w, 1.00167406f);
        p = fmaf(p, w, 2.83297682f);
    }
    return p * x;
}

__device__ __forceinline__ float lk(float v) { return v >= 0.0f ? v : 0.01f * v; }

// u in [0,1) from raw bits, JAX convention
__device__ __forceinline__ float bits_to_unit(unsigned bits) {
    return __uint_as_float((bits >> 9) | 0x3f800000u) - 1.0f;
}

// ---------------- init kernel: state = [x | hid | zeros] ----------------
__global__ void nca_init(const float* __restrict__ x) {
    long long idx = (long long)blockIdx.x * blockDim.x + threadIdx.x;
    const long long N = (long long)B_ * NCC * PIX;
    if (idx >= N) return;
    int p  = (int)(idx & (PIX - 1));
    int ch = (int)((idx >> 12) % NCC);
    int b  = (int)(idx / ((long long)NCC * PIX));
    float v;
    if (ch < NIMG) {
        v = x[((long long)b * NIMG + ch) * PIX + p];
    } else if (ch < NIMG + NHID) {
        unsigned kh0, kh1;
        tf2x32(0u, 42u, 0u, 10000u, kh0, kh1);
        unsigned ih = ((unsigned)b * NHID + (unsigned)(ch - NIMG)) * PIX + (unsigned)p;
        const unsigned half = 524288u;
        unsigned c0, c1, o0, o1, bits;
        if (ih < half) { c0 = ih; c1 = ih + half; }
        else           { c0 = ih - half; c1 = ih; }
        tf2x32(kh0, kh1, c0, c1, o0, o1);
        bits = (ih < half) ? o0 : o1;
        float u = bits_to_unit(bits);
        const float lo = -0.99999994f;           // nextafterf(-1,0)
        float val = u * (1.0f - lo) + lo;
        val = fmaxf(lo, val);
        float nrm = 1.41421356237f * erfinv_xla(val);   // sqrt(2)*erfinv
        v = 0.5f + 0.225f * nrm;
    } else {
        v = 0.0f;
    }
    g_bufA[idx] = v;
}

// ---------------- weight transpose / pad kernel ----------------
__global__ void nca_prep(const float* __restrict__ w1,
                         const float* __restrict__ w2,
                         const float* __restrict__ w3) {
    int i = blockIdx.x * blockDim.x + threadIdx.x;
    if (i < 96 * 256) {
        int k = i >> 8, o = i & 255;
        g_w1t[i] = (k < INVEC) ? w1[o * INVEC + k] : 0.0f;
    } else if (i < 96 * 256 + 256 * 128) {
        int j = i - 96 * 256;
        int k = j >> 7, o = j & 127;
        g_w2t[j] = w2[o * 256 + k];
    } else if (i < 96 * 256 + 256 * 128 + 128 * 32) {
        int j = i - 96 * 256 - 256 * 128;
        int k = j >> 5, o = j & 31;
        g_w3t[j] = (o < NCC) ? w3[o * 128 + k] : 0.0f;
    }
}

// ---------------- shared memory layout (floats), stride 64 ----------------
#define S_WBA   0
#define S_WBB   4096
#define S_SROWS 4096
#define S_PERCS 9840
#define S_H1C   15984
#define S_FIRE  24176
#define S_TOTAL 24240
#define SMEM_BYTES (S_TOTAL * 4)   // 96,960 bytes -> 2 CTAs/SM

// issue one 4096-float (16KB) weight chunk via cp.async (4 segs/thread)
__device__ __forceinline__ void issue_chunk(int c, uint32_t uA, uint32_t uB,
                                            int tid) {
    uint32_t dst = (c & 1) ? uB : uA;
    if (c < 3) {                       // w1 cols 0..127, rows c*32..+32
        int kk = c * 32;
#pragma unroll
        for (int i = 0; i < 4; i++) {
            int seg = tid + 256 * i;
            int row = seg >> 5, c16 = seg & 31;
            cpa16(dst + seg * 16, g_w1t + (kk + row) * 256 + c16 * 4);
        }
    } else if (c < 7) {                // w2 rows (c-3)*32..+32
        const float* src = g_w2t + (c - 3) * 32 * 128;
#pragma unroll
        for (int i = 0; i < 4; i++) {
            int seg = tid + 256 * i;
            cpa16(dst + seg * 16, src + seg * 4);
        }
    } else if (c < 10) {               // w1 cols 128..255, rows (c-7)*32..+32
        int kk = (c - 7) * 32;
#pragma unroll
        for (int i = 0; i < 4; i++) {
            int seg = tid + 256 * i;
            int row = seg >> 5, c16 = seg & 31;
            cpa16(dst + seg * 16, g_w1t + (kk + row) * 256 + 128 + c16 * 4);
        }
    } else if (c < 14) {               // w2 rows 128+(c-10)*32..+32
        const float* src = g_w2t + (128 + (c - 10) * 32) * 128;
#pragma unroll
        for (int i = 0; i < 4; i++) {
            int seg = tid + 256 * i;
            cpa16(dst + seg * 16, src + seg * 4);
        }
    } else {                           // w3 whole (4096 floats)
#pragma unroll
        for (int i = 0; i < 4; i++) {
            int seg = tid + 256 * i;
            cpa16(dst + seg * 16, g_w3t + seg * 4);
        }
    }
    CP_COMMIT();
}

// ---------------- fused step kernel: one CTA per (b, row) ----------------
__global__ __launch_bounds__(NT, 2)
void nca_step(int parity, int step, const int* __restrict__ steps_p,
              const float* __restrict__ b1) {
    extern __shared__ float sm[];
    float* wbA   = sm + S_WBA;
    float* wbB   = sm + S_WBB;
    float* srows = sm + S_SROWS;
    float* percs = sm + S_PERCS;
    float* h1c   = sm + S_H1C;
    float* h2s   = sm + S_H1C;        // h2 aliases h1c (after final GEMM2 read)
    float* fires = sm + S_FIRE;

    const int tid = threadIdx.x;
    const int bid = blockIdx.x;
    const int b = bid >> 6;
    const int h = bid & 63;
    const int tx = tid & 7;           // 8 pixel-groups of 8
    const int ty = tid >> 3;          // 0..31 output groups

    const float* sin_ = parity ? g_bufB : g_bufA;
    float*       sout = parity ? g_bufA : g_bufB;
    const float* base_in  = sin_ + ((long long)b * NCC) * PIX + h * 64;
    float*       base_out = sout + ((long long)b * NCC) * PIX + h * 64;

    const int S = steps_p ? steps_p[0] : 20;
    if (step >= S) {   // pass-through keeps double-buffer parity valid
        for (int i = tid; i < NCC * 64; i += NT) {
            int ch = i >> 6, w = i & 63;
            base_out[ch * PIX + w] = base_in[ch * PIX + w];
        }
        return;
    }

    const uint32_t uWBA = (uint32_t)__cvta_generic_to_shared(wbA);
    const uint32_t uWBB = (uint32_t)__cvta_generic_to_shared(wbB);

    // ---- PROLOGUE: issue chunk 0 (w1 C0 sub0 -> wbA; wbA never aliased) ----
    issue_chunk(0, uWBA, uWBB, tid);

    // ---- stage 3 state rows (29ch x 3 x 66, zero-padded) ----
    for (int i = tid; i < NCC * 3 * 66; i += NT) {
        int ch = i / 198;
        int rem = i - ch * 198;
        int r = rem / 66;
        int c = rem - r * 66;
        int hh = h + r - 1;
        int ww = c - 1;
        float v = 0.0f;
        if (hh >= 0 && hh < 64 && ww >= 0 && ww < 64)
            v = sin_[((long long)b * NCC + ch) * PIX + hh * 64 + ww];
        srows[i] = v;
    }

    // ---- fire mask for this row (bit-exact JAX uniform < 0.5) ----
    if (tid < 64) {
        unsigned kf0, kf1;
        tf2x32(0u, 42u, 0u, (unsigned)step, kf0, kf1);   // fold_in(key(42), step)
        unsigned pix = ((unsigned)b * 64u + (unsigned)h) * 64u + (unsigned)tid;
        const unsigned half = 32768u;                    // n = 65536
        unsigned c0, c1, o0, o1;
        if (pix < half) { c0 = pix; c1 = pix + half; }
        else            { c0 = pix - half; c1 = pix; }
        tf2x32(kf0, kf1, c0, c1, o0, o1);
        unsigned bits = (pix < half) ? o0 : o1;
        float u = bits_to_unit(bits);
        fires[tid] = (u < 0.5f) ? 1.0f : 0.0f;
    }

    // ---- time channel + zero rows 88..95 ----
    float tval = (float)step / 100.0f;
    if (tid < 64) percs[87 * 64 + tid] = tval;
    for (int i = tid; i < 8 * 64; i += NT) percs[88 * 64 + i] = 0.0f;
    __syncthreads();                                     // srows staged

    // ---- perception: s, sobel-x, sobel-y ----
    for (int i = tid; i < NCC * 64; i += NT) {
        int ch = i >> 6, w = i & 63;
        const float* rp = srows + ch * 198;
        float tl = rp[w],       tc = rp[w + 1],       tr = rp[w + 2];
        float ml = rp[66 + w],                        mr = rp[66 + w + 2];
        float mc = rp[66 + w + 1];
        float bl = rp[132 + w], bc = rp[132 + w + 1], br = rp[132 + w + 2];
        float sx = ((tr - tl) + 2.0f * (mr - ml) + (br - bl)) * 0.125f;
        float sy = ((bl - tl) + 2.0f * (bc - tc) + (br - tr)) * 0.125f;
        percs[ch * 64 + w]        = mc;
        percs[(29 + ch) * 64 + w] = sx;
        percs[(58 + ch) * 64 + w] = sy;
    }
    // NOTE: no sync here; the first phase's sync (below) orders percs/srows.

    // =====================================================================
    // 15-chunk pipeline. Phase p: WAIT chunk p; sync; issue p+1; compute p.
    // chunks 0-2: GEMM1 half0 | 3-6: GEMM2 part0 | 7-9: GEMM1 half1 |
    // 10-13: GEMM2 part1 | 14: GEMM3 weights.
    // Tile shape: 4 outs (ty) x 8 pixels (tx) per thread.
    // =====================================================================

    u64 acc2[4][4];
#pragma unroll
    for (int c = 0; c < 4; c++)
#pragma unroll
        for (int q = 0; q < 4; q++) acc2[c][q] = 0ull;

    // ---------- GEMM1 body: 4 outs x 4 pairs, 32 k ----------
#define G1_BODY(WB, KK, ACC)                                                   \
    _Pragma("unroll")                                                          \
    for (int j = 0; j < 32; j++) {                                             \
        const float* ap = &percs[(KK + j) * 64 + (tx << 3)];                   \
        const ulonglong2 pva = *reinterpret_cast<const ulonglong2*>(ap);       \
        const ulonglong2 pvb = *reinterpret_cast<const ulonglong2*>(ap + 4);   \
        const float4 wq = *reinterpret_cast<const float4*>(                    \
            &(WB)[j * 128 + (ty << 2)]);                                       \
        u64 wv[4];                                                             \
        wv[0] = bcast2(wq.x); wv[1] = bcast2(wq.y);                            \
        wv[2] = bcast2(wq.z); wv[3] = bcast2(wq.w);                            \
        _Pragma("unroll")                                                      \
        for (int c = 0; c < 4; c++) {                                          \
            ACC[c][0] = ffma2(wv[c], pva.x, ACC[c][0]);                        \
            ACC[c][1] = ffma2(wv[c], pva.y, ACC[c][1]);                        \
            ACC[c][2] = ffma2(wv[c], pvb.x, ACC[c][2]);                        \
            ACC[c][3] = ffma2(wv[c], pvb.y, ACC[c][3]);                        \
        }                                                                      \
    }

    // ---------- GEMM2 body: 4 outs x 4 pairs, 32 k from h1c ----------
#define G2_BODY(WB, J0)                                                        \
    _Pragma("unroll")                                                          \
    for (int j = 0; j < 32; j++) {                                             \
        const float* ap = &h1c[(J0 + j) * 64 + (tx << 3)];                     \
        const ulonglong2 pva = *reinterpret_cast<const ulonglong2*>(ap);       \
        const ulonglong2 pvb = *reinterpret_cast<const ulonglong2*>(ap + 4);   \
        const float4 wq = *reinterpret_cast<const float4*>(                    \
            &(WB)[j * 128 + (ty << 2)]);                                       \
        u64 wv[4];                                                             \
        wv[0] = bcast2(wq.x); wv[1] = bcast2(wq.y);                            \
        wv[2] = bcast2(wq.z); wv[3] = bcast2(wq.w);                            \
        _Pragma("unroll")                                                      \
        for (int c = 0; c < 4; c++) {                                          \
            acc2[c][0] = ffma2(wv[c], pva.x, acc2[c][0]);                      \
            acc2[c][1] = ffma2(wv[c], pva.y, acc2[c][1]);                      \
            acc2[c][2] = ffma2(wv[c], pvb.x, acc2[c][2]);                      \
            acc2[c][3] = ffma2(wv[c], pvb.y, acc2[c][3]);                      \
        }                                                                      \
    }

    // epilogue helper: unpack 4 pairs, apply f, store 8 px
#define STORE8(DST, OL, A, BIAS, DO_LK)                                        \
    {                                                                          \
        float e0, e1, e2, e3, e4, e5, e6, e7;                                  \
        unpack2(A[0], e0, e1); unpack2(A[1], e2, e3);                          \
        unpack2(A[2], e4, e5); unpack2(A[3], e6, e7);                          \
        float4 v0, v1;                                                         \
        if (DO_LK) {                                                           \
            v0.x = lk(e0 + BIAS); v0.y = lk(e1 + BIAS);                        \
            v0.z = lk(e2 + BIAS); v0.w = lk(e3 + BIAS);                        \
            v1.x = lk(e4 + BIAS); v1.y = lk(e5 + BIAS);                        \
            v1.z = lk(e6 + BIAS); v1.w = lk(e7 + BIAS);                        \
        }                                                                      \
        *reinterpret_cast<float4*>(&(DST)[(OL) * 64 + (tx << 3)]) = v0;        \
        *reinterpret_cast<float4*>(&(DST)[(OL) * 64 + (tx << 3) + 4]) = v1;    \
    }

    // ---------------- GEMM1 half 0 (outs 0..127): phases 0..2 ----------------
    {
        u64 acc1[4][4];
#pragma unroll
        for (int c = 0; c < 4; c++)
#pragma unroll
            for (int q = 0; q < 4; q++) acc1[c][q] = 0ull;
#pragma unroll
        for (int ph = 0; ph < 3; ph++) {
            CP_WAIT0();
            __syncthreads();
            issue_chunk(ph + 1, uWBA, uWBB, tid);
            const float* wb = (ph & 1) ? wbB : wbA;
            G1_BODY(wb, ph * 32, acc1)
        }
#pragma unroll
        for (int c = 0; c < 4; c++) {
            int ol = (ty << 2) + c;                      // 0..127
            float bb = b1[ol];
            STORE8(h1c, ol, acc1[c], bb, 1)
        }
    }

    // ---------------- GEMM2 part 0 (k 0..127): phases 3..6 ----------------
#pragma unroll
    for (int ph = 0; ph < 4; ph++) {
        CP_WAIT0();
        __syncthreads();
        issue_chunk(ph + 4, uWBA, uWBB, tid);
        const float* wb = ((ph + 3) & 1) ? wbB : wbA;
        G2_BODY(wb, ph * 32)
    }

    // ---------------- GEMM1 half 1 (outs 128..255): phases 7..9 -------------
    {
        u64 acc1[4][4];
#pragma unroll
        for (int c = 0; c < 4; c++)
#pragma unroll
            for (int q = 0; q < 4; q++) acc1[c][q] = 0ull;
#pragma unroll
        for (int ph = 0; ph < 3; ph++) {
            CP_WAIT0();
            __syncthreads();
            issue_chunk(ph + 8, uWBA, uWBB, tid);
            const float* wb = ((ph + 7) & 1) ? wbB : wbA;
            G1_BODY(wb, ph * 32, acc1)
        }
#pragma unroll
        for (int c = 0; c < 4; c++) {
            int ol = (ty << 2) + c;                      // local 0..127
            float bb = b1[128 + ol];
            STORE8(h1c, ol, acc1[c], bb, 1)
        }
    }

    // ---------------- GEMM2 part 1 (k 128..255): phases 10..13 --------------
#pragma unroll
    for (int ph = 0; ph < 4; ph++) {
        CP_WAIT0();
        __syncthreads();
        issue_chunk(ph + 11, uWBA, uWBB, tid);           // 11..14 (14 = w3)
        const float* wb = ((ph + 10) & 1) ? wbB : wbA;
        G2_BODY(wb, ph * 32)
    }

    // ---------------- GEMM2 epilogue: h2 overwrites h1c ----------------
    __syncthreads();            // all h1c reads done before overwrite
#pragma unroll
    for (int c = 0; c < 4; c++) {
        int o = (ty << 2) + c;
        STORE8(h2s, o, acc2[c], 0.0f, 1)
    }
    CP_WAIT0();                 // w3 chunk (14 -> wbA) resident
    __syncthreads();            // h2 visible

    // ---------------- GEMM3: h2[128] x w3 -> dx[29] + update ----------------
    {
        u64 acc[4];
        acc[0] = 0ull; acc[1] = 0ull; acc[2] = 0ull; acc[3] = 0ull;

#pragma unroll 8
        for (int j = 0; j < 128; j++) {
            const float* ap = &h2s[j * 64 + (tx << 3)];
            const ulonglong2 pva = *reinterpret_cast<const ulonglong2*>(ap);
            const ulonglong2 pvb = *reinterpret_cast<const ulonglong2*>(ap + 4);
            u64 w0 = bcast2(wbA[j * 32 + ty]);
            acc[0] = ffma2(w0, pva.x, acc[0]);
            acc[1] = ffma2(w0, pva.y, acc[1]);
            acc[2] = ffma2(w0, pvb.x, acc[2]);
            acc[3] = ffma2(w0, pvb.y, acc[3]);
        }
        int ch = ty;                       // 0..31
        if (ch < NCC) {
            float d0, d1, d2, d3, d4, d5, d6, d7;
            unpack2(acc[0], d0, d1); unpack2(acc[1], d2, d3);
            unpack2(acc[2], d4, d5); unpack2(acc[3], d6, d7);
            float dv[8] = {d0, d1, d2, d3, d4, d5, d6, d7};
#pragma unroll
            for (int p = 0; p < 8; p++) {
                int w = (tx << 3) + p;
                float inv = base_in[ch * PIX + w];
                float outv;
                if (ch < NIMG) outv = inv;                       // chan_mask = 0
                else           outv = inv + dv[p] * fires[w];
                base_out[ch * PIX + w] = outv;
            }
        }
    }
#undef G1_BODY
#undef G2_BODY
#undef STORE8
}

// ---------------- readout: mean over HxW of class channels, softmax --------
__global__ void nca_reduce(float* __restrict__ out) {
    __shared__ float red[256];
    __shared__ float logit[NOUT];
    int b = blockIdx.x;
    int tid = threadIdx.x;
    for (int ch = 0; ch < NOUT; ch++) {
        float s = 0.0f;
        const float* src = g_bufA + ((long long)b * NCC + (NIMG + NHID + ch)) * PIX;
        for (int p = tid; p < PIX; p += 256) s += src[p];
        red[tid] = s;
        __syncthreads();
        for (int off = 128; off > 0; off >>= 1) {
            if (tid < off) red[tid] += red[tid + off];
            __syncthreads();
        }
        if (tid == 0) logit[ch] = red[0] * (1.0f / 4096.0f);
        __syncthreads();
    }
    if (tid == 0) {
        float m = -1e30f;
        for (int c = 0; c < NOUT; c++) m = fmaxf(m, logit[c]);
        float e[NOUT], sum = 0.0f;
        for (int c = 0; c < NOUT; c++) { e[c] = expf(logit[c] - m); sum += e[c]; }
        float inv = 1.0f / sum;
        for (int c = 0; c < NOUT; c++) out[b * NOUT + c] = e[c] * inv;
    }
}

// ---------------- launch ----------------
extern "C" void kernel_launch(void* const* d_in, const int* in_sizes, int n_in,
                              void* d_out, int out_size) {
    const float* x  = (const float*)d_in[0];
    const float* w1 = (const float*)d_in[1];
    const float* b1 = (const float*)d_in[2];
    const float* w2 = (const float*)d_in[3];
    const float* w3 = (const float*)d_in[4];
    const int* steps_p = (n_in > 5) ? (const int*)d_in[5] : nullptr;

    cudaFuncSetAttribute(nca_step, cudaFuncAttributeMaxDynamicSharedMemorySize,
                         SMEM_BYTES);

    // weight transpose + padding
    nca_prep<<<(96 * 256 + 256 * 128 + 128 * 32 + 255) / 256, 256>>>(w1, w2, w3);
    // state init (x | hid | zeros) into bufA
    {
        long long N = (long long)B_ * NCC * PIX;
        nca_init<<<(int)((N + 255) / 256), 256>>>(x);
    }
    // 20 fixed step launches, double buffered (device-side guard on steps)
    for (int s = 0; s < 20; s++) {
        nca_step<<<B_ * HW_, NT, SMEM_BYTES>>>(s & 1, s, steps_p, b1);
    }
    // readout
    nca_reduce<<<B_, 256>>>((float*)d_out);
    (void)in_sizes; (void)out_size;
}

// round 16
// speedup vs baseline: 1.8597x; 1.8597x over previous
#include <cuda_runtime.h>
#include <cstdint>

// ---------------- problem constants ----------------
#define NCC   29
#define NIMG  3
#define NHID  16
#define NOUT  10
#define B_    16
#define HW_   64
#define PIX   4096           // 64*64
#define INVEC 88             // 3*29+1
#define NT    256

typedef unsigned long long u64;

// ---------------- packed f32x2 helpers (bit-exact vs scalar FP32) ----------
__device__ __forceinline__ u64 bcast2(float a) {
    u64 r; asm("mov.b64 %0, {%1, %1};" : "=l"(r) : "f"(a)); return r;
}
__device__ __forceinline__ void unpack2(u64 v, float& a, float& b) {
    asm("mov.b64 {%0, %1}, %2;" : "=f"(a), "=f"(b) : "l"(v));
}
__device__ __forceinline__ u64 ffma2(u64 a, u64 b, u64 c) {
    u64 d; asm("fma.rn.f32x2 %0, %1, %2, %3;" : "=l"(d) : "l"(a), "l"(b), "l"(c));
    return d;
}

// ---------------- cp.async helpers ----------------
__device__ __forceinline__ void cpa16(uint32_t dst, const void* src) {
    asm volatile("cp.async.ca.shared.global [%0], [%1], 16;" :: "r"(dst), "l"(src));
}
#define CP_COMMIT() asm volatile("cp.async.commit_group;" ::: "memory")
#define CP_WAIT0()  asm volatile("cp.async.wait_group 0;" ::: "memory")

// ---------------- persistent device buffers (no allocation allowed) ----------
__device__ float g_bufA[B_ * NCC * PIX];
__device__ float g_bufB[B_ * NCC * PIX];
__device__ float g_w1t[96 * 256];    // [k(pad 96)][o=256]
__device__ float g_w2t[256 * 128];   // [k=256][o=128]
__device__ float g_w3t[128 * 32];    // [k=128][o(pad 32)]

// ---------------- JAX threefry2x32 (bit exact) ----------------
__device__ __forceinline__ void tf2x32(unsigned k0, unsigned k1,
                                       unsigned x0, unsigned x1,
                                       unsigned& o0, unsigned& o1) {
    unsigned ks2 = k0 ^ k1 ^ 0x1BD11BDAu;
    x0 += k0; x1 += k1;
#define TFR(r) { x0 += x1; x1 = (x1 << (r)) | (x1 >> (32 - (r))); x1 ^= x0; }
    TFR(13) TFR(15) TFR(26) TFR(6)
    x0 += k1;  x1 += ks2 + 1u;
    TFR(17) TFR(29) TFR(16) TFR(24)
    x0 += ks2; x1 += k0 + 2u;
    TFR(13) TFR(15) TFR(26) TFR(6)
    x0 += k0;  x1 += k1 + 3u;
    TFR(17) TFR(29) TFR(16) TFR(24)
    x0 += k1;  x1 += ks2 + 4u;
    TFR(13) TFR(15) TFR(26) TFR(6)
    x0 += ks2; x1 += k0 + 5u;
#undef TFR
    o0 = x0; o1 = x1;
}

// XLA ErfInv32 (Giles polynomials) — matches jax.random.normal
__device__ __forceinline__ float erfinv_xla(float x) {
    float w = -log1pf(-x * x);
    float p;
    if (w < 5.0f) {
        w -= 2.5f;
        p = 2.81022636e-08f;
        p = fmaf(p, w, 3.43273939e-07f);
        p = fmaf(p, w, -3.5233877e-06f);
        p = fmaf(p, w, -4.39150654e-06f);
        p = fmaf(p, w, 0.00021858087f);
        p = fmaf(p, w, -0.00125372503f);
        p = fmaf(p, w, -0.00417768164f);
        p = fmaf(p, w, 0.246640727f);
        p = fmaf(p, w, 1.50140941f);
    } else {
        w = sqrtf(w) - 3.0f;
        p = -0.000200214257f;
        p = fmaf(p, w, 0.000100950558f);
        p = fmaf(p, w, 0.00134934322f);
        p = fmaf(p, w, -0.00367342844f);
        p = fmaf(p, w, 0.00573950773f);
        p = fmaf(p, w, -0.0076224613f);
        p = fmaf(p, w, 0.00943887047f);
        p = fmaf(p, w, 1.00167406f);
        p = fmaf(p, w, 2.83297682f);
    }
    return p * x;
}

__device__ __forceinline__ float lk(float v) { return v >= 0.0f ? v : 0.01f * v; }

// u in [0,1) from raw bits, JAX convention
__device__ __forceinline__ float bits_to_unit(unsigned bits) {
    return __uint_as_float((bits >> 9) | 0x3f800000u) - 1.0f;
}

// ---------------- init kernel: state = [x | hid | zeros] ----------------
__global__ void nca_init(const float* __restrict__ x) {
    long long idx = (long long)blockIdx.x * blockDim.x + threadIdx.x;
    const long long N = (long long)B_ * NCC * PIX;
    if (idx >= N) return;
    int p  = (int)(idx & (PIX - 1));
    int ch = (int)((idx >> 12) % NCC);
    int b  = (int)(idx / ((long long)NCC * PIX));
    float v;
    if (ch < NIMG) {
        v = x[((long long)b * NIMG + ch) * PIX + p];
    } else if (ch < NIMG + NHID) {
        unsigned kh0, kh1;
        tf2x32(0u, 42u, 0u, 10000u, kh0, kh1);
        unsigned ih = ((unsigned)b * NHID + (unsigned)(ch - NIMG)) * PIX + (unsigned)p;
        const unsigned half = 524288u;
        unsigned c0, c1, o0, o1, bits;
        if (ih < half) { c0 = ih; c1 = ih + half; }
        else           { c0 = ih - half; c1 = ih; }
        tf2x32(kh0, kh1, c0, c1, o0, o1);
        bits = (ih < half) ? o0 : o1;
        float u = bits_to_unit(bits);
        const float lo = -0.99999994f;           // nextafterf(-1,0)
        float val = u * (1.0f - lo) + lo;
        val = fmaxf(lo, val);
        float nrm = 1.41421356237f * erfinv_xla(val);   // sqrt(2)*erfinv
        v = 0.5f + 0.225f * nrm;
    } else {
        v = 0.0f;
    }
    g_bufA[idx] = v;
}

// ---------------- weight transpose / pad kernel ----------------
__global__ void nca_prep(const float* __restrict__ w1,
                         const float* __restrict__ w2,
                         const float* __restrict__ w3) {
    int i = blockIdx.x * blockDim.x + threadIdx.x;
    if (i < 96 * 256) {
        int k = i >> 8, o = i & 255;
        g_w1t[i] = (k < INVEC) ? w1[o * INVEC + k] : 0.0f;
    } else if (i < 96 * 256 + 256 * 128) {
        int j = i - 96 * 256;
        int k = j >> 7, o = j & 127;
        g_w2t[j] = w2[o * 256 + k];
    } else if (i < 96 * 256 + 256 * 128 + 128 * 32) {
        int j = i - 96 * 256 - 256 * 128;
        int k = j >> 5, o = j & 31;
        g_w3t[j] = (o < NCC) ? w3[o * 128 + k] : 0.0f;
    }
}

// ---------------- shared memory layout (floats), stride 64 ----------------
#define S_WBA   0
#define S_WBB   4096
#define S_SROWS 4096
#define S_PERCS 9840
#define S_H1C   15984
#define S_FIRE  24176
#define S_TOTAL 24240
#define SMEM_BYTES (S_TOTAL * 4)   // 96,960 bytes -> 2 CTAs/SM

// issue one 4096-float (16KB) weight chunk via cp.async (4 segs/thread)
__device__ __forceinline__ void issue_chunk(int c, uint32_t uA, uint32_t uB,
                                            int tid) {
    uint32_t dst = (c & 1) ? uB : uA;
    if (c < 3) {                       // w1 cols 0..127, rows c*32..+32
        int kk = c * 32;
#pragma unroll
        for (int i = 0; i < 4; i++) {
            int seg = tid + 256 * i;
            int row = seg >> 5, c16 = seg & 31;
            cpa16(dst + seg * 16, g_w1t + (kk + row) * 256 + c16 * 4);
        }
    } else if (c < 7) {                // w2 rows (c-3)*32..+32
        const float* src = g_w2t + (c - 3) * 32 * 128;
#pragma unroll
        for (int i = 0; i < 4; i++) {
            int seg = tid + 256 * i;
            cpa16(dst + seg * 16, src + seg * 4);
        }
    } else if (c < 10) {               // w1 cols 128..255, rows (c-7)*32..+32
        int kk = (c - 7) * 32;
#pragma unroll
        for (int i = 0; i < 4; i++) {
            int seg = tid + 256 * i;
            int row = seg >> 5, c16 = seg & 31;
            cpa16(dst + seg * 16, g_w1t + (kk + row) * 256 + 128 + c16 * 4);
        }
    } else if (c < 14) {               // w2 rows 128+(c-10)*32..+32
        const float* src = g_w2t + (128 + (c - 10) * 32) * 128;
#pragma unroll
        for (int i = 0; i < 4; i++) {
            int seg = tid + 256 * i;
            cpa16(dst + seg * 16, src + seg * 4);
        }
    } else {                           // w3 whole (4096 floats)
#pragma unroll
        for (int i = 0; i < 4; i++) {
            int seg = tid + 256 * i;
            cpa16(dst + seg * 16, g_w3t + seg * 4);
        }
    }
    CP_COMMIT();
}

// ---------------- fused step kernel: one CTA per (b, row) ----------------
__global__ __launch_bounds__(NT, 2)
void nca_step(int parity, int step, const int* __restrict__ steps_p,
              const float* __restrict__ b1) {
    extern __shared__ float sm[];
    float* wbA   = sm + S_WBA;
    float* wbB   = sm + S_WBB;
    float* srows = sm + S_SROWS;
    float* percs = sm + S_PERCS;
    float* h1c   = sm + S_H1C;
    float* h2s   = sm + S_H1C;        // h2 aliases h1c (after final GEMM2 read)
    float* fires = sm + S_FIRE;

    const int tid = threadIdx.x;
    const int bid = blockIdx.x;
    const int b = bid >> 6;
    const int h = bid & 63;
    const int tx = tid & 15;          // 16 pixel-groups of 4 (lane-contiguous)
    const int ty = tid >> 4;          // 0..15 output groups of 8

    const float* sin_ = parity ? g_bufB : g_bufA;
    float*       sout = parity ? g_bufA : g_bufB;
    const float* base_in  = sin_ + ((long long)b * NCC) * PIX + h * 64;
    float*       base_out = sout + ((long long)b * NCC) * PIX + h * 64;

    const int S = steps_p ? steps_p[0] : 20;
    if (step >= S) {   // pass-through keeps double-buffer parity valid
        for (int i = tid; i < NCC * 64; i += NT) {
            int ch = i >> 6, w = i & 63;
            base_out[ch * PIX + w] = base_in[ch * PIX + w];
        }
        return;
    }

    const uint32_t uWBA = (uint32_t)__cvta_generic_to_shared(wbA);
    const uint32_t uWBB = (uint32_t)__cvta_generic_to_shared(wbB);

    // ---- PROLOGUE: issue chunk 0 (w1 C0 sub0 -> wbA; wbA never aliased) ----
    issue_chunk(0, uWBA, uWBB, tid);

    // ---- stage 3 state rows (29ch x 3 x 66, zero-padded) ----
    for (int i = tid; i < NCC * 3 * 66; i += NT) {
        int ch = i / 198;
        int rem = i - ch * 198;
        int r = rem / 66;
        int c = rem - r * 66;
        int hh = h + r - 1;
        int ww = c - 1;
        float v = 0.0f;
        if (hh >= 0 && hh < 64 && ww >= 0 && ww < 64)
            v = sin_[((long long)b * NCC + ch) * PIX + hh * 64 + ww];
        srows[i] = v;
    }

    // ---- fire mask for this row (bit-exact JAX uniform < 0.5) ----
    if (tid < 64) {
        unsigned kf0, kf1;
        tf2x32(0u, 42u, 0u, (unsigned)step, kf0, kf1);   // fold_in(key(42), step)
        unsigned pix = ((unsigned)b * 64u + (unsigned)h) * 64u + (unsigned)tid;
        const unsigned half = 32768u;                    // n = 65536
        unsigned c0, c1, o0, o1;
        if (pix < half) { c0 = pix; c1 = pix + half; }
        else            { c0 = pix - half; c1 = pix; }
        tf2x32(kf0, kf1, c0, c1, o0, o1);
        unsigned bits = (pix < half) ? o0 : o1;
        float u = bits_to_unit(bits);
        fires[tid] = (u < 0.5f) ? 1.0f : 0.0f;
    }

    // ---- time channel + zero rows 88..95 ----
    float tval = (float)step / 100.0f;
    if (tid < 64) percs[87 * 64 + tid] = tval;
    for (int i = tid; i < 8 * 64; i += NT) percs[88 * 64 + i] = 0.0f;
    __syncthreads();                                     // srows staged

    // ---- perception: s, sobel-x, sobel-y ----
    for (int i = tid; i < NCC * 64; i += NT) {
        int ch = i >> 6, w = i & 63;
        const float* rp = srows + ch * 198;
        float tl = rp[w],       tc = rp[w + 1],       tr = rp[w + 2];
        float ml = rp[66 + w],                        mr = rp[66 + w + 2];
        float mc = rp[66 + w + 1];
        float bl = rp[132 + w], bc = rp[132 + w + 1], br = rp[132 + w + 2];
        float sx = ((tr - tl) + 2.0f * (mr - ml) + (br - bl)) * 0.125f;
        float sy = ((bl - tl) + 2.0f * (bc - tc) + (br - tr)) * 0.125f;
        percs[ch * 64 + w]        = mc;
        percs[(29 + ch) * 64 + w] = sx;
        percs[(58 + ch) * 64 + w] = sy;
    }
    // NOTE: no sync here; the first phase's sync (below) orders percs/srows.

    // =====================================================================
    // 15-chunk pipeline. Phase p: WAIT chunk p; sync; issue p+1; compute p.
    // chunks 0-2: GEMM1 half0 | 3-6: GEMM2 part0 | 7-9: GEMM1 half1 |
    // 10-13: GEMM2 part1 | 14: GEMM3 weights.
    // Lane mapping: f32x2 lanes = OUT-PAIRS (weights loaded as natural u64
    // pairs, zero weight MOVs); activation scalar broadcast (4 MOV/j).
    // Tile: 8 outs (ty, as 4 out-pairs) x 4 px (tx) per thread.
    // =====================================================================

    u64 acc2[4][4];                   // [out-pair][pixel]
#pragma unroll
    for (int c = 0; c < 4; c++)
#pragma unroll
        for (int q = 0; q < 4; q++) acc2[c][q] = 0ull;

    // ---------- GEMM body: 4 out-pairs x 4 px, 32 k ----------
#define G_BODY(SRC, WB, KK, ACC)                                               \
    _Pragma("unroll")                                                          \
    for (int j = 0; j < 32; j++) {                                             \
        const float4 av = *reinterpret_cast<const float4*>(                    \
            &(SRC)[(KK + j) * 64 + (tx << 2)]);                                \
        u64 a0 = bcast2(av.x), a1 = bcast2(av.y);                              \
        u64 a2 = bcast2(av.z), a3 = bcast2(av.w);                              \
        const ulonglong2 wp0 = *reinterpret_cast<const ulonglong2*>(           \
            &(WB)[j * 128 + (ty << 3)]);                                       \
        const ulonglong2 wp1 = *reinterpret_cast<const ulonglong2*>(           \
            &(WB)[j * 128 + (ty << 3) + 4]);                                   \
        u64 wv[4] = {wp0.x, wp0.y, wp1.x, wp1.y};                              \
        _Pragma("unroll")                                                      \
        for (int c = 0; c < 4; c++) {                                          \
            ACC[c][0] = ffma2(wv[c], a0, ACC[c][0]);                           \
            ACC[c][1] = ffma2(wv[c], a1, ACC[c][1]);                           \
            ACC[c][2] = ffma2(wv[c], a2, ACC[c][2]);                           \
            ACC[c][3] = ffma2(wv[c], a3, ACC[c][3]);                           \
        }                                                                      \
    }

    // epilogue: acc[op][px] lanes = (out 2op, 2op+1). Regroup per out, store
    // float4 over the thread's 4 pixels. OBASE = global out index of ty*8.
#define EPILOG(DST, ACC, OBASE, USE_BIAS)                                      \
    _Pragma("unroll")                                                          \
    for (int c = 0; c < 4; c++) {                                              \
        int o0 = (ty << 3) + 2 * c;                                            \
        float lo0, hi0, lo1, hi1, lo2, hi2, lo3, hi3;                          \
        unpack2(ACC[c][0], lo0, hi0); unpack2(ACC[c][1], lo1, hi1);            \
        unpack2(ACC[c][2], lo2, hi2); unpack2(ACC[c][3], lo3, hi3);            \
        float bb0 = (USE_BIAS) ? b1[(OBASE) + 2 * c]     : 0.0f;               \
        float bb1 = (USE_BIAS) ? b1[(OBASE) + 2 * c + 1] : 0.0f;               \
        float4 v0, v1;                                                         \
        v0.x = lk(lo0 + bb0); v0.y = lk(lo1 + bb0);                            \
        v0.z = lk(lo2 + bb0); v0.w = lk(lo3 + bb0);                            \
        v1.x = lk(hi0 + bb1); v1.y = lk(hi1 + bb1);                            \
        v1.z = lk(hi2 + bb1); v1.w = lk(hi3 + bb1);                            \
        *reinterpret_cast<float4*>(&(DST)[o0 * 64 + (tx << 2)]) = v0;          \
        *reinterpret_cast<float4*>(&(DST)[(o0 + 1) * 64 + (tx << 2)]) = v1;    \
    }

    // ---------------- GEMM1 half 0 (outs 0..127): phases 0..2 ----------------
    {
        u64 acc1[4][4];
#pragma unroll
        for (int c = 0; c < 4; c++)
#pragma unroll
            for (int q = 0; q < 4; q++) acc1[c][q] = 0ull;
#pragma unroll
        for (int ph = 0; ph < 3; ph++) {
            CP_WAIT0();
            __syncthreads();
            issue_chunk(ph + 1, uWBA, uWBB, tid);
            const float* wb = (ph & 1) ? wbB : wbA;
            G_BODY(percs, wb, ph * 32, acc1)
        }
        EPILOG(h1c, acc1, (ty << 3), 1)
    }

    // ---------------- GEMM2 part 0 (k 0..127): phases 3..6 ----------------
#pragma unroll
    for (int ph = 0; ph < 4; ph++) {
        CP_WAIT0();
        __syncthreads();
        issue_chunk(ph + 4, uWBA, uWBB, tid);
        const float* wb = ((ph + 3) & 1) ? wbB : wbA;
        G_BODY(h1c, wb, ph * 32, acc2)
    }

    // ---------------- GEMM1 half 1 (outs 128..255): phases 7..9 -------------
    {
        u64 acc1[4][4];
#pragma unroll
        for (int c = 0; c < 4; c++)
#pragma unroll
            for (int q = 0; q < 4; q++) acc1[c][q] = 0ull;
#pragma unroll
        for (int ph = 0; ph < 3; ph++) {
            CP_WAIT0();
            __syncthreads();
            issue_chunk(ph + 8, uWBA, uWBB, tid);
            const float* wb = ((ph + 7) & 1) ? wbB : wbA;
            G_BODY(percs, wb, ph * 32, acc1)
        }
        EPILOG(h1c, acc1, 128 + (ty << 3), 1)
    }

    // ---------------- GEMM2 part 1 (k 128..255): phases 10..13 --------------
#pragma unroll
    for (int ph = 0; ph < 4; ph++) {
        CP_WAIT0();
        __syncthreads();
        issue_chunk(ph + 11, uWBA, uWBB, tid);           // 11..14 (14 = w3)
        const float* wb = ((ph + 10) & 1) ? wbB : wbA;
        G_BODY(h1c, wb, ph * 32, acc2)
    }

    // ---------------- GEMM2 epilogue: h2 overwrites h1c ----------------
    __syncthreads();            // all h1c reads done before overwrite
    EPILOG(h2s, acc2, 0, 0)     // OBASE unused when USE_BIAS=0
    CP_WAIT0();                 // w3 chunk (14 -> wbA) resident
    __syncthreads();            // h2 visible

    // ---------------- GEMM3: h2[128] x w3 -> dx[29] + update ----------------
    // out-pair lanes here too: weights (w[2c], w[2c+1]) contiguous -> u64.
    {
        u64 acc[4];               // [pixel], lanes = (ch 2ty, 2ty+1)
        acc[0] = 0ull; acc[1] = 0ull; acc[2] = 0ull; acc[3] = 0ull;

#pragma unroll 8
        for (int j = 0; j < 128; j++) {
            const float4 av = *reinterpret_cast<const float4*>(
                &h2s[j * 64 + (tx << 2)]);
            u64 wp = *reinterpret_cast<const u64*>(&wbA[j * 32 + (ty << 1)]);
            acc[0] = ffma2(wp, bcast2(av.x), acc[0]);
            acc[1] = ffma2(wp, bcast2(av.y), acc[1]);
            acc[2] = ffma2(wp, bcast2(av.z), acc[2]);
            acc[3] = ffma2(wp, bcast2(av.w), acc[3]);
        }
        float l0, h0, l1, h1v, l2, h2v, l3, h3;
        unpack2(acc[0], l0, h0); unpack2(acc[1], l1, h1v);
        unpack2(acc[2], l2, h2v); unpack2(acc[3], l3, h3);
        float dva[4] = {l0, l1, l2, l3};    // ch = 2*ty
        float dvb[4] = {h0, h1v, h2v, h3};  // ch = 2*ty+1
#pragma unroll
        for (int c = 0; c < 2; c++) {
            int ch = (ty << 1) + c;
            const float* dv = c ? dvb : dva;
            if (ch < NCC) {
#pragma unroll
                for (int p = 0; p < 4; p++) {
                    int w = (tx << 2) + p;
                    float inv = base_in[ch * PIX + w];
                    float outv;
                    if (ch < NIMG) outv = inv;                       // chan_mask = 0
                    else           outv = inv + dv[p] * fires[w];
                    base_out[ch * PIX + w] = outv;
                }
            }
        }
    }
#undef G_BODY
#undef EPILOG
}

// ---------------- readout: mean over HxW of class channels, softmax --------
__global__ void nca_reduce(float* __restrict__ out) {
    __shared__ float red[256];
    __shared__ float logit[NOUT];
    int b = blockIdx.x;
    int tid = threadIdx.x;
    for (int ch = 0; ch < NOUT; ch++) {
        float s = 0.0f;
        const float* src = g_bufA + ((long long)b * NCC + (NIMG + NHID + ch)) * PIX;
        for (int p = tid; p < PIX; p += 256) s += src[p];
        red[tid] = s;
        __syncthreads();
        for (int off = 128; off > 0; off >>= 1) {
            if (tid < off) red[tid] += red[tid + off];
            __syncthreads();
        }
        if (tid == 0) logit[ch] = red[0] * (1.0f / 4096.0f);
        __syncthreads();
    }
    if (tid == 0) {
        float m = -1e30f;
        for (int c = 0; c < NOUT; c++) m = fmaxf(m, logit[c]);
        float e[NOUT], sum = 0.0f;
        for (int c = 0; c < NOUT; c++) { e[c] = expf(logit[c] - m); sum += e[c]; }
        float inv = 1.0f / sum;
        for (int c = 0; c < NOUT; c++) out[b * NOUT + c] = e[c] * inv;
    }
}

// ---------------- launch ----------------
extern "C" void kernel_launch(void* const* d_in, const int* in_sizes, int n_in,
                              void* d_out, int out_size) {
    const float* x  = (const float*)d_in[0];
    const float* w1 = (const float*)d_in[1];
    const float* b1 = (const float*)d_in[2];
    const float* w2 = (const float*)d_in[3];
    const float* w3 = (const float*)d_in[4];
    const int* steps_p = (n_in > 5) ? (const int*)d_in[5] : nullptr;

    cudaFuncSetAttribute(nca_step, cudaFuncAttributeMaxDynamicSharedMemorySize,
                         SMEM_BYTES);

    // weight transpose + padding
    nca_prep<<<(96 * 256 + 256 * 128 + 128 * 32 + 255) / 256, 256>>>(w1, w2, w3);
    // state init (x | hid | zeros) into bufA
    {
        long long N = (long long)B_ * NCC * PIX;
        nca_init<<<(int)((N + 255) / 256), 256>>>(x);
    }
    // 20 fixed step launches, double buffered (device-side guard on steps)
    for (int s = 0; s < 20; s++) {
        nca_step<<<B_ * HW_, NT, SMEM_BYTES>>>(s & 1, s, steps_p, b1);
    }
    // readout
    nca_reduce<<<B_, 256>>>((float*)d_out);
    (void)in_sizes; (void)out_size;
}